// round 4
// baseline (speedup 1.0000x reference)
#include <cuda_runtime.h>

// Problem constants
#define B_  2
#define S_  2048
#define D_  1024
#define H_  16
#define HD_ 64

#define LDW 68   // padded shared row width for attention tiles

// ---------------------------------------------------------------------------
// Scratch (static __device__ arrays; no dynamic allocation allowed)
// ---------------------------------------------------------------------------
__device__ float g_qkv [(size_t)B_ * S_ * 3 * D_];   // [B,S,3D]   50 MB
__device__ float g_q   [(size_t)B_ * H_ * S_ * HD_]; // [B,H,S,HD] 17 MB
__device__ float g_k   [(size_t)B_ * H_ * S_ * HD_];
__device__ float g_v   [(size_t)B_ * H_ * S_ * HD_];
__device__ float g_vals[(size_t)B_ * S_ * D_];       // [B,S,D]    17 MB

// ---------------------------------------------------------------------------
// Tiled SGEMM (NT): C[m,n] = bias[n] + sum_k A[m,k] * Bw[n,k]
// Tiles: 128x128x8, 256 threads, 8x8 per thread.
// Aext==nullptr -> A = g_vals ; Cext==nullptr -> C = g_qkv
// ---------------------------------------------------------------------------
__global__ __launch_bounds__(256)
void gemm_nt(const float* __restrict__ Aext, const float* __restrict__ Bw,
             const float* __restrict__ bias, float* __restrict__ Cext,
             int N, int K)
{
    const float* A = Aext ? Aext : g_vals;
    float*       C = Cext ? Cext : g_qkv;

    __shared__ float As[8][128];
    __shared__ float Bs[8][128];

    const int tid = threadIdx.x;
    const int bm = blockIdx.y * 128;
    const int bn = blockIdx.x * 128;
    const int tx = tid & 15;
    const int ty = tid >> 4;
    const int row0 = ty * 8;
    const int col0 = tx * 8;

    float acc[8][8];
#pragma unroll
    for (int i = 0; i < 8; i++)
#pragma unroll
        for (int j = 0; j < 8; j++) acc[i][j] = 0.f;

    const int lr = tid >> 1;          // 0..127 : tile row
    const int lk = (tid & 1) << 2;    // 0 or 4 : k offset
    const float* Ap = A  + (size_t)(bm + lr) * K + lk;
    const float* Bp = Bw + (size_t)(bn + lr) * K + lk;

    for (int k0 = 0; k0 < K; k0 += 8) {
        float4 av = *(const float4*)(Ap + k0);
        float4 bv = *(const float4*)(Bp + k0);
        As[lk + 0][lr] = av.x; As[lk + 1][lr] = av.y;
        As[lk + 2][lr] = av.z; As[lk + 3][lr] = av.w;
        Bs[lk + 0][lr] = bv.x; Bs[lk + 1][lr] = bv.y;
        Bs[lk + 2][lr] = bv.z; Bs[lk + 3][lr] = bv.w;
        __syncthreads();
#pragma unroll
        for (int kk = 0; kk < 8; kk++) {
            float a[8], b[8];
            *(float4*)(a)     = *(const float4*)&As[kk][row0];
            *(float4*)(a + 4) = *(const float4*)&As[kk][row0 + 4];
            *(float4*)(b)     = *(const float4*)&Bs[kk][col0];
            *(float4*)(b + 4) = *(const float4*)&Bs[kk][col0 + 4];
#pragma unroll
            for (int i = 0; i < 8; i++)
#pragma unroll
                for (int j = 0; j < 8; j++)
                    acc[i][j] += a[i] * b[j];
        }
        __syncthreads();
    }

#pragma unroll
    for (int i = 0; i < 8; i++) {
        float* Cp = C + (size_t)(bm + row0 + i) * N + bn + col0;
#pragma unroll
        for (int j = 0; j < 8; j++)
            Cp[j] = acc[i][j] + bias[bn + col0 + j];
    }
}

// ---------------------------------------------------------------------------
// RoPE + split qkv -> q,k (rotated), v in [B,H,S,HD] layout.
// qkv column layout: head h occupies cols [h*192, h*192+192): q | k | v (64 each).
// rotate_half over last dim 64: out[d<32] = -t[d+32]; out[d>=32] = t[d-32]
// ---------------------------------------------------------------------------
__global__ __launch_bounds__(256)
void rope_split(const float* __restrict__ sp)
{
    int i = blockIdx.x * 256 + threadIdx.x;   // over B*S*H*HD = 2^22
    int d = i & 63;
    int h = (i >> 6) & 15;
    int s = (i >> 10) & 2047;
    int b = i >> 21;

    const float* base = g_qkv + (size_t)(b * S_ + s) * (3 * D_) + h * 192;
    float spv = sp[s * 64 + d];
    float c  = cosf(spv);
    float sn = sinf(spv);
    int   rot   = (d < 32) ? (d + 32) : (d - 32);
    float rsign = (d < 32) ? -1.f : 1.f;

    float qv = base[d],       qr = base[rot];
    float kv = base[64 + d],  kr = base[64 + rot];
    float vv = base[128 + d];

    size_t o = ((size_t)((b * H_ + h) * S_) + s) * HD_ + d;
    g_q[o] = qv * c + rsign * qr * sn;
    g_k[o] = kv * c + rsign * kr * sn;
    g_v[o] = vv;
}

// ---------------------------------------------------------------------------
// Fused flash attention (fp32, online softmax).
// Block: 256 threads, 64 q-rows, loops over 32 K-tiles of 64.
// logits = (QK^T + pos_bias) / 8 ; masked -> -9e15 ; softmax ; O = P V
// Output written in [B,S,H*HD] layout directly (ready for out-proj GEMM).
// ---------------------------------------------------------------------------
__global__ __launch_bounds__(256)
void attn_fused(const float* __restrict__ pb, const int* __restrict__ mask)
{
    extern __shared__ float smem[];
    float* Qst  = smem;               // [64][LDW] Q transposed: Qst[d][r]
    float* KPst = smem + 64 * LDW;    // K transposed, then reused as P^T
    float* Vs   = smem + 2 * 64 * LDW;// [64][LDW] V row-major: Vs[k][c]

    const int b  = blockIdx.y;
    const int h  = blockIdx.z;
    const int q0 = blockIdx.x * 64;
    const int tid = threadIdx.x;
    const int tx = tid & 15;
    const int ty = tid >> 4;
    const int r0 = ty * 4;            // this thread's 4 q-rows
    const int c0 = tx * 4;            // this thread's 4 k-cols / O-dims
    const size_t hb = (size_t)(b * H_ + h) * S_ * HD_;

    // Load Q tile transposed
#pragma unroll
    for (int i = 0; i < 4; i++) {
        int idx = tid + i * 256;
        int r = idx >> 4;
        int dd = (idx & 15) << 2;
        float4 qv = *(const float4*)(g_q + hb + (size_t)(q0 + r) * HD_ + dd);
        Qst[(dd + 0) * LDW + r] = qv.x;
        Qst[(dd + 1) * LDW + r] = qv.y;
        Qst[(dd + 2) * LDW + r] = qv.z;
        Qst[(dd + 3) * LDW + r] = qv.w;
    }

    float acc[4][4];
    float m_i[4], l_i[4];
#pragma unroll
    for (int i = 0; i < 4; i++) {
        m_i[i] = -1e30f; l_i[i] = 0.f;
#pragma unroll
        for (int j = 0; j < 4; j++) acc[i][j] = 0.f;
    }

    for (int kt = 0; kt < S_ / 64; kt++) {
        const int k0 = kt * 64;
        __syncthreads();   // previous tile's P/V reads done
        // Load K tile (transposed) and V tile
#pragma unroll
        for (int i = 0; i < 4; i++) {
            int idx = tid + i * 256;
            int r = idx >> 4;
            int dd = (idx & 15) << 2;
            float4 kv = *(const float4*)(g_k + hb + (size_t)(k0 + r) * HD_ + dd);
            KPst[(dd + 0) * LDW + r] = kv.x;
            KPst[(dd + 1) * LDW + r] = kv.y;
            KPst[(dd + 2) * LDW + r] = kv.z;
            KPst[(dd + 3) * LDW + r] = kv.w;
            float4 vv = *(const float4*)(g_v + hb + (size_t)(k0 + r) * HD_ + dd);
            *(float4*)&Vs[r * LDW + dd] = vv;
        }
        __syncthreads();

        // S = Q K^T  (4x4 per thread)
        float s[4][4];
#pragma unroll
        for (int i = 0; i < 4; i++)
#pragma unroll
            for (int j = 0; j < 4; j++) s[i][j] = 0.f;
#pragma unroll
        for (int d = 0; d < 64; d++) {
            float qa[4], kb[4];
            *(float4*)qa = *(const float4*)&Qst [d * LDW + r0];
            *(float4*)kb = *(const float4*)&KPst[d * LDW + c0];
#pragma unroll
            for (int i = 0; i < 4; i++)
#pragma unroll
                for (int j = 0; j < 4; j++)
                    s[i][j] += qa[i] * kb[j];
        }

        // bias + scale + mask
#pragma unroll
        for (int i = 0; i < 4; i++) {
            const size_t roff = ((size_t)h * S_ + (q0 + r0 + i)) * S_ + k0 + c0;
            float pbv[4]; *(float4*)pbv = *(const float4*)(pb + roff);
            int4 mk = *(const int4*)(mask + (size_t)(q0 + r0 + i) * S_ + k0 + c0);
            int mkv[4] = {mk.x, mk.y, mk.z, mk.w};
#pragma unroll
            for (int j = 0; j < 4; j++)
                s[i][j] = (mkv[j] == 0) ? -9.0e15f : (s[i][j] + pbv[j]) * 0.125f;
        }

        // online softmax (row stats reduced over 16 lanes sharing ty)
        float alpha[4];
#pragma unroll
        for (int i = 0; i < 4; i++) {
            float rm = fmaxf(fmaxf(s[i][0], s[i][1]), fmaxf(s[i][2], s[i][3]));
#pragma unroll
            for (int o = 8; o > 0; o >>= 1)
                rm = fmaxf(rm, __shfl_xor_sync(0xffffffffu, rm, o));
            float mnew = fmaxf(m_i[i], rm);
            alpha[i] = __expf(m_i[i] - mnew);
            float rs = 0.f;
#pragma unroll
            for (int j = 0; j < 4; j++) {
                s[i][j] = __expf(s[i][j] - mnew);
                rs += s[i][j];
            }
#pragma unroll
            for (int o = 8; o > 0; o >>= 1)
                rs += __shfl_xor_sync(0xffffffffu, rs, o);
            l_i[i] = l_i[i] * alpha[i] + rs;
            m_i[i] = mnew;
        }

        __syncthreads();   // all K^T reads done; safe to overwrite with P^T
#pragma unroll
        for (int i = 0; i < 4; i++)
#pragma unroll
            for (int j = 0; j < 4; j++) {
                KPst[(c0 + j) * LDW + (r0 + i)] = s[i][j];
                acc[i][j] *= alpha[i];
            }
        __syncthreads();

        // O += P V
#pragma unroll
        for (int kk = 0; kk < 64; kk++) {
            float pa[4], vb[4];
            *(float4*)pa = *(const float4*)&KPst[kk * LDW + r0];
            *(float4*)vb = *(const float4*)&Vs  [kk * LDW + c0];
#pragma unroll
            for (int i = 0; i < 4; i++)
#pragma unroll
                for (int j = 0; j < 4; j++)
                    acc[i][j] += pa[i] * vb[j];
        }
    }

    // normalize and store into [B,S,D] (head-interleaved) scratch
#pragma unroll
    for (int i = 0; i < 4; i++) {
        float inv = 1.f / l_i[i];
        float4 o4 = make_float4(acc[i][0] * inv, acc[i][1] * inv,
                                acc[i][2] * inv, acc[i][3] * inv);
        *(float4*)(g_vals + ((size_t)(b * S_) + q0 + r0 + i) * D_ + h * HD_ + c0) = o4;
    }
}

// ---------------------------------------------------------------------------
// Launch
// ---------------------------------------------------------------------------
extern "C" void kernel_launch(void* const* d_in, const int* in_sizes, int n_in,
                              void* d_out, int out_size)
{
    const float* x    = (const float*)d_in[0];
    const float* pb   = (const float*)d_in[1];
    const float* sp   = (const float*)d_in[2];
    const int*   mask = (const int*)  d_in[3];
    const float* Wqkv = (const float*)d_in[4];
    const float* bqkv = (const float*)d_in[5];
    const float* Wo   = (const float*)d_in[6];
    const float* bo   = (const float*)d_in[7];
    float* out = (float*)d_out;

    const int attn_smem = 3 * 64 * LDW * (int)sizeof(float);  // 52224 B
    cudaFuncSetAttribute(attn_fused,
                         cudaFuncAttributeMaxDynamicSharedMemorySize, attn_smem);

    // 1) QKV projection: [4096,3072] = x[4096,1024] @ Wqkv^T + b
    gemm_nt<<<dim3((3 * D_) / 128, (B_ * S_) / 128), 256>>>(
        x, Wqkv, bqkv, nullptr /* -> g_qkv */, 3 * D_, D_);

    // 2) RoPE + split into q,k,v [B,H,S,HD]
    rope_split<<<(B_ * S_ * D_) / 256, 256>>>(sp);

    // 3) Fused attention -> g_vals [B,S,D]
    attn_fused<<<dim3(S_ / 64, B_, H_), 256, attn_smem>>>(pb, mask);

    // 4) Output projection: out[4096,1024] = g_vals @ Wo^T + bo
    gemm_nt<<<dim3(D_ / 128, (B_ * S_) / 128), 256>>>(
        nullptr /* g_vals */, Wo, bo, out, D_, D_);
}

// round 5
// speedup vs baseline: 1.0007x; 1.0007x over previous
#include <cuda_runtime.h>

// Problem constants
#define B_  2
#define S_  2048
#define D_  1024
#define H_  16
#define HD_ 64

#define LDW 68   // padded shared row width for attention tiles

// ---------------------------------------------------------------------------
// Scratch (static __device__ arrays; no dynamic allocation allowed)
// ---------------------------------------------------------------------------
__device__ float g_qkv [(size_t)B_ * S_ * 3 * D_];   // [B,S,3D]   50 MB
__device__ float g_q   [(size_t)B_ * H_ * S_ * HD_]; // [B,H,S,HD] 17 MB
__device__ float g_k   [(size_t)B_ * H_ * S_ * HD_];
__device__ float g_v   [(size_t)B_ * H_ * S_ * HD_];
__device__ float g_vals[(size_t)B_ * S_ * D_];       // [B,S,D]    17 MB

// ---------------------------------------------------------------------------
// Tiled SGEMM (NT): C[m,n] = bias[n] + sum_k A[m,k] * Bw[n,k]
// Tiles: 128x128x8, 256 threads, 8x8 per thread.
// Aext==nullptr -> A = g_vals ; Cext==nullptr -> C = g_qkv
// ---------------------------------------------------------------------------
__global__ __launch_bounds__(256)
void gemm_nt(const float* __restrict__ Aext, const float* __restrict__ Bw,
             const float* __restrict__ bias, float* __restrict__ Cext,
             int N, int K)
{
    const float* A = Aext ? Aext : g_vals;
    float*       C = Cext ? Cext : g_qkv;

    __shared__ float As[8][128];
    __shared__ float Bs[8][128];

    const int tid = threadIdx.x;
    const int bm = blockIdx.y * 128;
    const int bn = blockIdx.x * 128;
    const int tx = tid & 15;
    const int ty = tid >> 4;
    const int row0 = ty * 8;
    const int col0 = tx * 8;

    float acc[8][8];
#pragma unroll
    for (int i = 0; i < 8; i++)
#pragma unroll
        for (int j = 0; j < 8; j++) acc[i][j] = 0.f;

    const int lr = tid >> 1;          // 0..127 : tile row
    const int lk = (tid & 1) << 2;    // 0 or 4 : k offset
    const float* Ap = A  + (size_t)(bm + lr) * K + lk;
    const float* Bp = Bw + (size_t)(bn + lr) * K + lk;

    for (int k0 = 0; k0 < K; k0 += 8) {
        float4 av = *(const float4*)(Ap + k0);
        float4 bv = *(const float4*)(Bp + k0);
        As[lk + 0][lr] = av.x; As[lk + 1][lr] = av.y;
        As[lk + 2][lr] = av.z; As[lk + 3][lr] = av.w;
        Bs[lk + 0][lr] = bv.x; Bs[lk + 1][lr] = bv.y;
        Bs[lk + 2][lr] = bv.z; Bs[lk + 3][lr] = bv.w;
        __syncthreads();
#pragma unroll
        for (int kk = 0; kk < 8; kk++) {
            float a[8], b[8];
            *(float4*)(a)     = *(const float4*)&As[kk][row0];
            *(float4*)(a + 4) = *(const float4*)&As[kk][row0 + 4];
            *(float4*)(b)     = *(const float4*)&Bs[kk][col0];
            *(float4*)(b + 4) = *(const float4*)&Bs[kk][col0 + 4];
#pragma unroll
            for (int i = 0; i < 8; i++)
#pragma unroll
                for (int j = 0; j < 8; j++)
                    acc[i][j] += a[i] * b[j];
        }
        __syncthreads();
    }

#pragma unroll
    for (int i = 0; i < 8; i++) {
        float* Cp = C + (size_t)(bm + row0 + i) * N + bn + col0;
#pragma unroll
        for (int j = 0; j < 8; j++)
            Cp[j] = acc[i][j] + bias[bn + col0 + j];
    }
}

// ---------------------------------------------------------------------------
// RoPE + split qkv -> q,k (rotated), v in [B,H,S,HD] layout.
// qkv column layout: head h occupies cols [h*192, h*192+192): q | k | v (64 each).
// rotate_half over last dim 64: out[d<32] = -t[d+32]; out[d>=32] = t[d-32]
// ---------------------------------------------------------------------------
__global__ __launch_bounds__(256)
void rope_split(const float* __restrict__ sp)
{
    int i = blockIdx.x * 256 + threadIdx.x;   // over B*S*H*HD = 2^22
    int d = i & 63;
    int h = (i >> 6) & 15;
    int s = (i >> 10) & 2047;
    int b = i >> 21;

    const float* base = g_qkv + (size_t)(b * S_ + s) * (3 * D_) + h * 192;
    float spv = sp[s * 64 + d];
    float c  = cosf(spv);
    float sn = sinf(spv);
    int   rot   = (d < 32) ? (d + 32) : (d - 32);
    float rsign = (d < 32) ? -1.f : 1.f;

    float qv = base[d],       qr = base[rot];
    float kv = base[64 + d],  kr = base[64 + rot];
    float vv = base[128 + d];

    size_t o = ((size_t)((b * H_ + h) * S_) + s) * HD_ + d;
    g_q[o] = qv * c + rsign * qr * sn;
    g_k[o] = kv * c + rsign * kr * sn;
    g_v[o] = vv;
}

// ---------------------------------------------------------------------------
// Fused flash attention (fp32, online softmax).
// Block: 256 threads, 64 q-rows, loops over 32 K-tiles of 64.
// logits = (QK^T + pos_bias) / 8 ; masked -> -9e15 ; softmax ; O = P V
// Output written in [B,S,H*HD] layout directly (ready for out-proj GEMM).
// ---------------------------------------------------------------------------
__global__ __launch_bounds__(256)
void attn_fused(const float* __restrict__ pb, const int* __restrict__ mask)
{
    extern __shared__ float smem[];
    float* Qst  = smem;               // [64][LDW] Q transposed: Qst[d][r]
    float* KPst = smem + 64 * LDW;    // K transposed, then reused as P^T
    float* Vs   = smem + 2 * 64 * LDW;// [64][LDW] V row-major: Vs[k][c]

    const int b  = blockIdx.y;
    const int h  = blockIdx.z;
    const int q0 = blockIdx.x * 64;
    const int tid = threadIdx.x;
    const int tx = tid & 15;
    const int ty = tid >> 4;
    const int r0 = ty * 4;            // this thread's 4 q-rows
    const int c0 = tx * 4;            // this thread's 4 k-cols / O-dims
    const size_t hb = (size_t)(b * H_ + h) * S_ * HD_;

    // Load Q tile transposed
#pragma unroll
    for (int i = 0; i < 4; i++) {
        int idx = tid + i * 256;
        int r = idx >> 4;
        int dd = (idx & 15) << 2;
        float4 qv = *(const float4*)(g_q + hb + (size_t)(q0 + r) * HD_ + dd);
        Qst[(dd + 0) * LDW + r] = qv.x;
        Qst[(dd + 1) * LDW + r] = qv.y;
        Qst[(dd + 2) * LDW + r] = qv.z;
        Qst[(dd + 3) * LDW + r] = qv.w;
    }

    float acc[4][4];
    float m_i[4], l_i[4];
#pragma unroll
    for (int i = 0; i < 4; i++) {
        m_i[i] = -1e30f; l_i[i] = 0.f;
#pragma unroll
        for (int j = 0; j < 4; j++) acc[i][j] = 0.f;
    }

    for (int kt = 0; kt < S_ / 64; kt++) {
        const int k0 = kt * 64;
        __syncthreads();   // previous tile's P/V reads done
        // Load K tile (transposed) and V tile
#pragma unroll
        for (int i = 0; i < 4; i++) {
            int idx = tid + i * 256;
            int r = idx >> 4;
            int dd = (idx & 15) << 2;
            float4 kv = *(const float4*)(g_k + hb + (size_t)(k0 + r) * HD_ + dd);
            KPst[(dd + 0) * LDW + r] = kv.x;
            KPst[(dd + 1) * LDW + r] = kv.y;
            KPst[(dd + 2) * LDW + r] = kv.z;
            KPst[(dd + 3) * LDW + r] = kv.w;
            float4 vv = *(const float4*)(g_v + hb + (size_t)(k0 + r) * HD_ + dd);
            *(float4*)&Vs[r * LDW + dd] = vv;
        }
        __syncthreads();

        // S = Q K^T  (4x4 per thread)
        float s[4][4];
#pragma unroll
        for (int i = 0; i < 4; i++)
#pragma unroll
            for (int j = 0; j < 4; j++) s[i][j] = 0.f;
#pragma unroll
        for (int d = 0; d < 64; d++) {
            float qa[4], kb[4];
            *(float4*)qa = *(const float4*)&Qst [d * LDW + r0];
            *(float4*)kb = *(const float4*)&KPst[d * LDW + c0];
#pragma unroll
            for (int i = 0; i < 4; i++)
#pragma unroll
                for (int j = 0; j < 4; j++)
                    s[i][j] += qa[i] * kb[j];
        }

        // bias + scale + mask
#pragma unroll
        for (int i = 0; i < 4; i++) {
            const size_t roff = ((size_t)h * S_ + (q0 + r0 + i)) * S_ + k0 + c0;
            float pbv[4]; *(float4*)pbv = *(const float4*)(pb + roff);
            int4 mk = *(const int4*)(mask + (size_t)(q0 + r0 + i) * S_ + k0 + c0);
            int mkv[4] = {mk.x, mk.y, mk.z, mk.w};
#pragma unroll
            for (int j = 0; j < 4; j++)
                s[i][j] = (mkv[j] == 0) ? -9.0e15f : (s[i][j] + pbv[j]) * 0.125f;
        }

        // online softmax (row stats reduced over 16 lanes sharing ty)
        float alpha[4];
#pragma unroll
        for (int i = 0; i < 4; i++) {
            float rm = fmaxf(fmaxf(s[i][0], s[i][1]), fmaxf(s[i][2], s[i][3]));
#pragma unroll
            for (int o = 8; o > 0; o >>= 1)
                rm = fmaxf(rm, __shfl_xor_sync(0xffffffffu, rm, o));
            float mnew = fmaxf(m_i[i], rm);
            alpha[i] = __expf(m_i[i] - mnew);
            float rs = 0.f;
#pragma unroll
            for (int j = 0; j < 4; j++) {
                s[i][j] = __expf(s[i][j] - mnew);
                rs += s[i][j];
            }
#pragma unroll
            for (int o = 8; o > 0; o >>= 1)
                rs += __shfl_xor_sync(0xffffffffu, rs, o);
            l_i[i] = l_i[i] * alpha[i] + rs;
            m_i[i] = mnew;
        }

        __syncthreads();   // all K^T reads done; safe to overwrite with P^T
#pragma unroll
        for (int i = 0; i < 4; i++)
#pragma unroll
            for (int j = 0; j < 4; j++) {
                KPst[(c0 + j) * LDW + (r0 + i)] = s[i][j];
                acc[i][j] *= alpha[i];
            }
        __syncthreads();

        // O += P V
#pragma unroll
        for (int kk = 0; kk < 64; kk++) {
            float pa[4], vb[4];
            *(float4*)pa = *(const float4*)&KPst[kk * LDW + r0];
            *(float4*)vb = *(const float4*)&Vs  [kk * LDW + c0];
#pragma unroll
            for (int i = 0; i < 4; i++)
#pragma unroll
                for (int j = 0; j < 4; j++)
                    acc[i][j] += pa[i] * vb[j];
        }
    }

    // normalize and store into [B,S,D] (head-interleaved) scratch
#pragma unroll
    for (int i = 0; i < 4; i++) {
        float inv = 1.f / l_i[i];
        float4 o4 = make_float4(acc[i][0] * inv, acc[i][1] * inv,
                                acc[i][2] * inv, acc[i][3] * inv);
        *(float4*)(g_vals + ((size_t)(b * S_) + q0 + r0 + i) * D_ + h * HD_ + c0) = o4;
    }
}

// ---------------------------------------------------------------------------
// Launch
// ---------------------------------------------------------------------------
extern "C" void kernel_launch(void* const* d_in, const int* in_sizes, int n_in,
                              void* d_out, int out_size)
{
    const float* x    = (const float*)d_in[0];
    const float* pb   = (const float*)d_in[1];
    const float* sp   = (const float*)d_in[2];
    const int*   mask = (const int*)  d_in[3];
    const float* Wqkv = (const float*)d_in[4];
    const float* bqkv = (const float*)d_in[5];
    const float* Wo   = (const float*)d_in[6];
    const float* bo   = (const float*)d_in[7];
    float* out = (float*)d_out;

    const int attn_smem = 3 * 64 * LDW * (int)sizeof(float);  // 52224 B
    cudaFuncSetAttribute(attn_fused,
                         cudaFuncAttributeMaxDynamicSharedMemorySize, attn_smem);

    // 1) QKV projection: [4096,3072] = x[4096,1024] @ Wqkv^T + b
    gemm_nt<<<dim3((3 * D_) / 128, (B_ * S_) / 128), 256>>>(
        x, Wqkv, bqkv, nullptr /* -> g_qkv */, 3 * D_, D_);

    // 2) RoPE + split into q,k,v [B,H,S,HD]
    rope_split<<<(B_ * S_ * D_) / 256, 256>>>(sp);

    // 3) Fused attention -> g_vals [B,S,D]
    attn_fused<<<dim3(S_ / 64, B_, H_), 256, attn_smem>>>(pb, mask);

    // 4) Output projection: out[4096,1024] = g_vals @ Wo^T + bo
    gemm_nt<<<dim3(D_ / 128, (B_ * S_) / 128), 256>>>(
        nullptr /* g_vals */, Wo, bo, out, D_, D_);
}